// round 15
// baseline (speedup 1.0000x reference)
#include <cuda_runtime.h>
#include <cuda_fp16.h>
#include <cstdint>

// Transposed conv (full conv): B=8, H=W=256, CIN=COUT=64, 3x3, fp32 NHWC.
// out[b,p,q,co] = sum_{di,dj,ci} in[b,p-di,q-dj,ci] * ker[ci,co,di,dj]
// Single persistent kernel:
//   Phase 1: fp32->fp16 preconvert (pre-swizzled) to __device__ global;
//            tail columns (q=256,257) on CTAs 0..64 (reduced convert quota).
//   Global ticket barrier (all CTAs co-resident, 1 CTA/SM).
//   Phase 2: mma.sync fp16 implicit GEMM; rows via cp.async; 768 threads,
//            warp tile 16px x 32co x 2 rows with rolling A window.

#define IH 256
#define IW 256
#define NCH 64
#define OH 258
#define OW 258

// smem layout
#define B_TAP 8192                        // per tap: 64 co rows x 128B fp16
#define SM_B 0
#define SM_A (9 * B_TAP)                  // 73728
#define A_SLOT 8704                       // 68 px segs * 128B
#define NSLOT 16
#define SM_TOTAL (SM_A + NSLOT * A_SLOT)  // 212992

#define NPB 43                            // 6-row units per strip (43*6=258)
#define NSTRIP 32                         // 8 b * 4 q-strips of 64
#define NMAIN (NSTRIP * NPB)              // 1376
#define NROWS (8 * IH)                    // 2048 convert rows
#define NTPX (8 * OH * 2)                 // 4128 tail pixels
#define NTAIL 65
#define NTHR 768

#define GROW 32768                        // bytes per pre-converted input row

// 64MB pre-converted fp16 input: [b][r][pa][ci], 128B per px, SW128 by abs px
__device__ __align__(128) unsigned char g_fp16[(size_t)8 * IH * GROW];
__device__ unsigned int g_bar;            // epoch ticket barrier

__device__ __forceinline__ uint32_t smem_u32(const void* p) {
    uint32_t a;
    asm("{ .reg .u64 t; cvta.to.shared.u64 t, %1; cvt.u32.u64 %0, t; }" : "=r"(a) : "l"(p));
    return a;
}
__device__ __forceinline__ void ldm4(uint32_t* r, uint32_t a) {
    asm volatile("ldmatrix.sync.aligned.m8n8.x4.shared.b16 {%0,%1,%2,%3}, [%4];"
                 : "=r"(r[0]), "=r"(r[1]), "=r"(r[2]), "=r"(r[3]) : "r"(a));
}
__device__ __forceinline__ void mma16816(float* c, const uint32_t* a,
                                         uint32_t b0, uint32_t b1) {
    asm volatile(
        "mma.sync.aligned.m16n8k16.row.col.f32.f16.f16.f32 "
        "{%0,%1,%2,%3}, {%4,%5,%6,%7}, {%8,%9}, {%0,%1,%2,%3};"
        : "+f"(c[0]), "+f"(c[1]), "+f"(c[2]), "+f"(c[3])
        : "r"(a[0]), "r"(a[1]), "r"(a[2]), "r"(a[3]), "r"(b0), "r"(b1));
}
__device__ __forceinline__ void cp16(uint32_t dst, const void* src) {
    asm volatile(
        "{ .reg .u64 g; cvta.to.global.u64 g, %1; cp.async.cg.shared.global [%0], [g], 16; }"
        :: "r"(dst), "l"(src) : "memory");
}
__device__ __forceinline__ void cpcommit() {
    asm volatile("cp.async.commit_group;" ::: "memory");
}
template <int N>
__device__ __forceinline__ void cpwait() {
    asm volatile("cp.async.wait_group %0;" :: "n"(N) : "memory");
}

__global__ void __launch_bounds__(NTHR, 1)
tconv_fused_kernel(const float* __restrict__ gin, const float* __restrict__ gw,
                   float* __restrict__ gout)
{
    extern __shared__ char smem[];
    const uint32_t sb = smem_u32(smem);
    const int tid = threadIdx.x;
    const int lane = tid & 31;
    const int wid = tid >> 5;
    const int bid = blockIdx.x;
    const int g = gridDim.x;

    // ---- weight convert: gw[ci][co][tap] -> smem W^T[co][ci] fp16 ----
    for (int e = tid; e < NCH * NCH; e += NTHR) {
        int ci = e >> 6, co = e & 63;
        const float* wp = gw + (size_t)e * 9;
        uint32_t off = (uint32_t)co * 128 + (uint32_t)ci * 2;
        uint32_t sw = off ^ ((off >> 3) & 0x70);
#pragma unroll
        for (int tap = 0; tap < 9; tap++) {
            __half h = __float2half_rn(wp[tap]);
            *(unsigned short*)(smem + SM_B + tap * B_TAP + sw) = __half_as_ushort(h);
        }
    }

    // ldmatrix lane maps
    const int lm = (lane & 7) + ((lane >> 3) & 1) * 8;
    const uint32_t kcl = (uint32_t)((lane >> 4) & 1) * 16;

    // ================= PHASE 1: preconvert (+ tail on CTAs 0..64) ===========
    {
        // capacity: tail CTAs (bid < 65) convert fewer rows (9 vs 17 units)
        long long Pa = 17LL * bid - 8LL * (bid < 65 ? bid : 65);
        long long Pb = 17LL * (bid + 1) - 8LL * (bid + 1 < 65 ? bid + 1 : 65);
        long long C = 17LL * g - 8LL * 65;
        int r0 = (int)((NROWS * Pa) / C);
        int r1 = (int)((NROWS * Pb) / C);
        for (int R = r0; R < r1; R++) {
            const int b = R >> 8, r = R & 255;
            const float* src = gin + ((size_t)b * IH + r) * IW * NCH;
            unsigned char* dst = g_fp16 + ((size_t)b * IH + r) * GROW;
#pragma unroll 2
            for (int idx = tid; idx < IW * 8; idx += NTHR) {
                int pa = idx >> 3, c8 = idx & 7;
                const float* s = src + (size_t)pa * NCH + c8 * 8;
                float4 v0 = __ldg((const float4*)s);
                float4 v1 = __ldg((const float4*)(s + 4));
                __half2 h01 = make_half2(__float2half_rn(v0.x), __float2half_rn(v0.y));
                __half2 h23 = make_half2(__float2half_rn(v0.z), __float2half_rn(v0.w));
                __half2 h45 = make_half2(__float2half_rn(v1.x), __float2half_rn(v1.y));
                __half2 h67 = make_half2(__float2half_rn(v1.z), __float2half_rn(v1.w));
                uint32_t off = (uint32_t)pa * 128 + (uint32_t)c8 * 16;
                uint32_t sw = off ^ ((off >> 3) & 0x70);
                *(uint4*)(dst + sw) = make_uint4(*(uint32_t*)&h01, *(uint32_t*)&h23,
                                                 *(uint32_t*)&h45, *(uint32_t*)&h67);
            }
        }
    }

    // ---- tail units (independent of g_fp16): CTAs 0..64 ----
    if (bid < NTAIL) {
        const int g0 = bid * 64;
        const int tm = wid & 3;
        const int tn = (wid >> 2) & 1;
        const bool tact = (wid < 8);

        const int tnl0 = tn * 32 + lm;
        const int tnl1 = tnl0 + 16;
        const uint32_t tbrow0 = (uint32_t)tnl0 * 128, tbm0 = (uint32_t)(tnl0 & 7) << 4;
        const uint32_t tbrow1 = (uint32_t)tnl1 * 128, tbm1 = (uint32_t)(tnl1 & 7) << 4;
        const int rowi = tm * 16 + lm;
        const uint32_t arow = (uint32_t)rowi * 128;
        const uint32_t am = (uint32_t)(rowi & 7) << 4;

        float ct[4][4];
#pragma unroll
        for (int i = 0; i < 4; i++)
#pragma unroll
            for (int j = 0; j < 4; j++) ct[i][j] = 0.f;

        for (int tap = 0; tap < 9; tap++) {
            const int di = tap / 3, dj = tap % 3;
            __syncthreads();   // weight build / prev tap reads done
            for (int idx = tid; idx < 64 * 16; idx += NTHR) {
                int m = idx >> 4, c4 = idx & 15;
                int gg = g0 + m;
                int bb_ = gg / (OH * 2);
                int rem = gg - bb_ * (OH * 2);
                int p = rem >> 1;
                int qq = 256 + (rem & 1);
                int r = p - di, cc = qq - dj;
                float4 v = make_float4(0.f, 0.f, 0.f, 0.f);
                if (gg < NTPX && r >= 0 && r < IH && cc < IW)
                    v = __ldg((const float4*)(gin +
                        ((((size_t)bb_ * IH + r) * IW + cc) * NCH) + c4 * 4));
                __half2 h01 = make_half2(__float2half_rn(v.x), __float2half_rn(v.y));
                __half2 h23 = make_half2(__float2half_rn(v.z), __float2half_rn(v.w));
                uint32_t off = (uint32_t)m * 128 + (uint32_t)c4 * 8;
                uint32_t sw = off ^ ((off >> 3) & 0x70);
                *(uint2*)(smem + SM_A + sw) = make_uint2(*(uint32_t*)&h01, *(uint32_t*)&h23);
            }
            __syncthreads();

            if (tact) {
                const uint32_t bb = sb + SM_B + (uint32_t)tap * B_TAP;
#pragma unroll
                for (int s = 0; s < 4; s++) {
                    const uint32_t kx = (uint32_t)s * 32 + kcl;
                    uint32_t B0[4], B1[4], A[4];
                    ldm4(B0, bb + tbrow0 + (kx ^ tbm0));
                    ldm4(B1, bb + tbrow1 + (kx ^ tbm1));
                    ldm4(A, sb + SM_A + arow + (kx ^ am));
                    mma16816(ct[0], A, B0[0], B0[2]);
                    mma16816(ct[1], A, B0[1], B0[3]);
                    mma16816(ct[2], A, B1[0], B1[2]);
                    mma16816(ct[3], A, B1[1], B1[3]);
                }
            }
        }

        if (tact) {
            const int m0 = tm * 16 + (lane >> 2);
#pragma unroll
            for (int half = 0; half < 2; half++) {
                const int gg = g0 + m0 + half * 8;
                if (gg < NTPX) {
                    const int bb_ = gg / (OH * 2);
                    const int rem = gg - bb_ * (OH * 2);
                    const int p = rem >> 1;
                    const int qq = 256 + (rem & 1);
                    float* orow = gout + (((size_t)bb_ * OH + p) * OW + qq) * NCH;
#pragma unroll
                    for (int nt = 0; nt < 4; nt++) {
                        const int co = tn * 32 + nt * 8 + (lane & 3) * 2;
                        *(float2*)(orow + co) =
                            make_float2(ct[nt][half * 2], ct[nt][half * 2 + 1]);
                    }
                }
            }
        }
    }

    // ================= global ticket barrier =================
    __threadfence();
    __syncthreads();
    if (tid == 0) {
        unsigned int old = atomicAdd(&g_bar, 1u);
        unsigned int target = (old / (unsigned)g) * (unsigned)g + (unsigned)g;
        while (true) {
            unsigned int cur;
            asm volatile("ld.acquire.gpu.u32 %0, [%1];"
                         : "=r"(cur) : "l"(&g_bar) : "memory");
            if (cur >= target) break;
            __nanosleep(128);
        }
    }
    __syncthreads();

    // ================= PHASE 2: main MMA loop =================
    const int warp_m = wid & 3;          // 16-px group
    const int warp_n = (wid >> 2) & 1;   // 32-co group
    const int warp_g = wid >> 3;         // row-pair 0..2

    const int nl0 = warp_n * 32 + lm;
    const int nl1 = nl0 + 16;
    const uint32_t brow0 = (uint32_t)nl0 * 128, bm0 = (uint32_t)(nl0 & 7) << 4;
    const uint32_t brow1 = (uint32_t)nl1 * 128, bm1 = (uint32_t)(nl1 & 7) << 4;

    const int u0 = (int)(((long long)bid * NMAIN) / g);
    const int u1 = (int)(((long long)(bid + 1) * NMAIN) / g);
    int cur_strip = -1;

    for (int u = u0; u < u1; u++) {
        const int strip = u / NPB;
        const int pb = u - strip * NPB;
        const int p0 = pb * 6;
        const int b = strip >> 2;
        const int qg0 = (strip & 3) * 64;

        bool pf = false;
        if (strip != cur_strip) {
            cpwait<0>();
            __syncthreads();   // prior reads done before slot overwrite
            int rlo = p0 - 2 < 0 ? 0 : p0 - 2;
            int rhi = p0 + 5 > IH - 1 ? IH - 1 : p0 + 5;
            for (int r = rlo; r <= rhi; r++) {
                const uint32_t dslot = sb + SM_A + (uint32_t)(r & 15) * A_SLOT;
                const unsigned char* srow = g_fp16 + ((size_t)b * IH + r) * GROW;
                for (int idx = tid; idx < 544; idx += NTHR) {
                    int j = idx >> 3, ch = idx & 7;
                    int pa = qg0 - 2 + j;
                    uint32_t d = dslot + (uint32_t)j * 128 + (uint32_t)ch * 16;
                    if (pa >= 0 && pa < IW)
                        cp16(d, srow + (size_t)pa * 128 + ch * 16);
                    else
                        *(uint4*)(smem + (d - sb)) = make_uint4(0, 0, 0, 0);
                }
            }
            cpcommit();
            cur_strip = strip;
        }
        if (u + 1 < u1 && (u + 1) / NPB == strip) {
            int rlo = p0 + 6;
            int rhi = p0 + 11 > IH - 1 ? IH - 1 : p0 + 11;
            for (int r = rlo; r <= rhi; r++) {
                const uint32_t dslot = sb + SM_A + (uint32_t)(r & 15) * A_SLOT;
                const unsigned char* srow = g_fp16 + ((size_t)b * IH + r) * GROW;
                for (int idx = tid; idx < 544; idx += NTHR) {
                    int j = idx >> 3, ch = idx & 7;
                    int pa = qg0 - 2 + j;
                    uint32_t d = dslot + (uint32_t)j * 128 + (uint32_t)ch * 16;
                    if (pa >= 0 && pa < IW)
                        cp16(d, srow + (size_t)pa * 128 + ch * 16);
                    else
                        *(uint4*)(smem + (d - sb)) = make_uint4(0, 0, 0, 0);
                }
            }
            cpcommit();
            pf = true;
        }
        if (pf) cpwait<1>(); else cpwait<0>();
        __syncthreads();   // this unit's rows visible to all warps

        // ---- compute: this warp's rows {pw, pw+1}, 16px x 32co each ----
        const int pw = p0 + warp_g * 2;
        float c[2][4][4];
#pragma unroll
        for (int rr = 0; rr < 2; rr++)
#pragma unroll
            for (int i = 0; i < 4; i++)
#pragma unroll
                for (int j = 0; j < 4; j++) c[rr][i][j] = 0.f;

        uint32_t aB[4];
        bool okA[4];
#pragma unroll
        for (int t = 0; t < 4; t++) {
            int rp = pw - 2 + t;
            okA[t] = (rp >= 0 && rp < IH);
            aB[t] = sb + SM_A + (uint32_t)(rp & 15) * A_SLOT;
        }

#pragma unroll
        for (int dj = 0; dj < 3; dj++) {
            const int rowi = warp_m * 16 + lm + 2 - dj;
            const uint32_t arow = (uint32_t)rowi * 128;
            const uint32_t am = (uint32_t)((rowi + 6) & 7) << 4;
#pragma unroll
            for (int s = 0; s < 4; s++) {
                const uint32_t kx = (uint32_t)s * 32 + kcl;
                const uint32_t ax = arow + (kx ^ am);
                uint32_t Ahi[4], Alo[4];
                if (okA[3]) ldm4(Ahi, aB[3] + ax);   // rp = pw+1
#pragma unroll
                for (int di = 0; di < 3; di++) {
                    const int tlo = 2 - di;
                    if (okA[tlo]) ldm4(Alo, aB[tlo] + ax);   // rp = pw-di
                    const uint32_t bb = sb + SM_B + (uint32_t)(di * 3 + dj) * B_TAP;
                    uint32_t B0[4], B1[4];
                    ldm4(B0, bb + brow0 + (kx ^ bm0));
                    ldm4(B1, bb + brow1 + (kx ^ bm1));
                    if (okA[tlo]) {
                        mma16816(c[0][0], Alo, B0[0], B0[2]);
                        mma16816(c[0][1], Alo, B0[1], B0[3]);
                        mma16816(c[0][2], Alo, B1[0], B1[2]);
                        mma16816(c[0][3], Alo, B1[1], B1[3]);
                    }
                    if (okA[tlo + 1]) {
                        mma16816(c[1][0], Ahi, B0[0], B0[2]);
                        mma16816(c[1][1], Ahi, B0[1], B0[3]);
                        mma16816(c[1][2], Ahi, B1[0], B1[2]);
                        mma16816(c[1][3], Ahi, B1[1], B1[3]);
                    }
#pragma unroll
                    for (int k = 0; k < 4; k++) Ahi[k] = Alo[k];
                }
            }
        }

        // ---- store both rows ----
        const int q = qg0 + warp_m * 16 + (lane >> 2);
#pragma unroll
        for (int rr = 0; rr < 2; rr++) {
            const int p = pw + rr;
            float* orow = gout + (((size_t)b * OH + p) * OW + q) * NCH;
#pragma unroll
            for (int nt = 0; nt < 4; nt++) {
                const int co = warp_n * 32 + nt * 8 + (lane & 3) * 2;
                *(float2*)(orow + co) = make_float2(c[rr][nt][0], c[rr][nt][1]);
                *(float2*)(orow + 8 * NCH + co) = make_float2(c[rr][nt][2], c[rr][nt][3]);
            }
        }
        __syncthreads();   // all reads done before next iter's cp.async writes
    }
}

extern "C" void kernel_launch(void* const* d_in, const int* in_sizes, int n_in,
                              void* d_out, int out_size)
{
    const float* gin = (const float*)d_in[0]; // [8,256,256,64]
    const float* gw  = (const float*)d_in[1]; // [64,64,3,3]
    float* gout = (float*)d_out;              // [8,258,258,64]

    static int nsm = 0;
    if (nsm == 0) {
        cudaDeviceGetAttribute(&nsm, cudaDevAttrMultiProcessorCount, 0);
        if (nsm <= 0) nsm = 148;
        cudaFuncSetAttribute(tconv_fused_kernel,
                             cudaFuncAttributeMaxDynamicSharedMemorySize, SM_TOTAL);
    }
    tconv_fused_kernel<<<nsm, NTHR, SM_TOTAL>>>(gin, gw, gout);
}